// round 1
// baseline (speedup 1.0000x reference)
#include <cuda_runtime.h>
#include <cstdint>

#define BB 2
#define LL 1024
#define DM 768
#define DI 1536
#define DS 16
#define DTR 48
#define XD 80            // DT_RANK + 2*D_STATE
#define NL 6
#define VOCAB_N 32000
#define DE 384
#define TOK (BB*LL)      // 2048

// ------------------------- scratch (no allocation allowed) -------------------
__device__ __align__(128) float g_hidden[TOK*DM];
__device__ __align__(128) float g_residual[TOK*DM];
__device__ __align__(128) float g_hs[TOK*DM];
__device__ __align__(128) float g_xz[TOK*2*DI];
__device__ __align__(128) float g_xconv[TOK*DI];
__device__ __align__(128) float g_xdbl[TOK*XD];
__device__ __align__(128) float g_dt[TOK*DI];
__device__ __align__(128) float g_y[TOK*DI];

// ------------------------- embed: concat(tok_emb, pos_emb), zero residual ----
__global__ void embed_kernel(const int* __restrict__ ids, const int* __restrict__ pos,
                             const float* __restrict__ emb, const float* __restrict__ pemb,
                             float* __restrict__ hidden, float* __restrict__ res)
{
    int idx = blockIdx.x * blockDim.x + threadIdx.x;
    if (idx >= TOK*DM) return;
    int t = idx / DM, c = idx % DM;
    float v;
    if (c < DE) v = emb[(size_t)ids[t]*DE + c];
    else        v = pemb[(size_t)pos[t]*DE + (c-DE)];
    hidden[idx] = v;
    res[idx] = 0.f;
}

// ------------------ fused: res += hidden ; out = rmsnorm(res)*w --------------
__global__ __launch_bounds__(256) void addnorm_kernel(
    const float* __restrict__ h, float* __restrict__ res,
    const float* __restrict__ w, float* __restrict__ out)
{
    int t = blockIdx.x;
    const float* hp = h + (size_t)t*DM;
    float* rp = res + (size_t)t*DM;
    float v[3];
    float ss = 0.f;
#pragma unroll
    for (int q = 0; q < 3; q++) {
        int i = threadIdx.x + q*256;
        v[q] = hp[i] + rp[i];
        ss += v[q]*v[q];
    }
#pragma unroll
    for (int o = 16; o > 0; o >>= 1) ss += __shfl_xor_sync(0xffffffffu, ss, o);
    __shared__ float red[8];
    if ((threadIdx.x & 31) == 0) red[threadIdx.x >> 5] = ss;
    __syncthreads();
    float tot = 0.f;
#pragma unroll
    for (int q = 0; q < 8; q++) tot += red[q];
    float rstd = rsqrtf(tot * (1.f/(float)DM) + 1e-5f);
#pragma unroll
    for (int q = 0; q < 3; q++) {
        int i = threadIdx.x + q*256;
        rp[i] = v[q];
        out[(size_t)t*DM + i] = v[q] * rstd * w[i];
    }
}

// ---------------- depthwise causal conv (width 4) + bias + silu --------------
__global__ void conv_silu_kernel(const float* __restrict__ xz,
                                 const float* __restrict__ cw,
                                 const float* __restrict__ cb,
                                 float* __restrict__ out)
{
    int idx = blockIdx.x * blockDim.x + threadIdx.x;
    if (idx >= TOK*DI) return;
    int d = idx % DI;
    int t = idx / DI;
    int l = t % LL;
    float acc = cb[d];
    const float* base = xz + (size_t)t*(2*DI) + d;
#pragma unroll
    for (int j = 0; j < 4; j++) {
        int ll = l - 3 + j;
        if (ll >= 0) acc += cw[d*4+j] * base[(j-3)*(2*DI)];
    }
    out[idx] = acc / (1.f + __expf(-acc));   // silu
}

// ---------------- selective scan: 16 lanes per (b,d) channel -----------------
__global__ __launch_bounds__(256) void scan_kernel(
    const float* __restrict__ xc, const float* __restrict__ dt,
    const float* __restrict__ xd, const float* __restrict__ xz,
    const float* __restrict__ A_log, const float* __restrict__ Dv,
    float* __restrict__ y)
{
    int tid = threadIdx.x;
    int p = blockIdx.x * 16 + (tid >> 4);   // (b,d) pair
    int n = tid & 15;
    int b = p / DI;
    int d = p - b*DI;
    float A = -__expf(A_log[d*DS + n]);
    float Dval = Dv[d];
    float h = 0.f;
    const float* xcb = xc + (size_t)b*LL*DI + d;
    const float* dtb = dt + (size_t)b*LL*DI + d;
    const float* xdb = xd + (size_t)b*LL*XD + DTR + n;   // B at +0, C at +DS
    const float* xzb = xz + (size_t)b*LL*(2*DI) + DI + d;
    float* yb = y + (size_t)b*LL*DI + d;
#pragma unroll 4
    for (int l = 0; l < LL; l++) {
        float xv  = xcb[l*DI];
        float dtv = dtb[l*DI];
        float Bv  = xdb[l*XD];
        float Cv  = xdb[l*XD + DS];
        float dA  = __expf(dtv * A);
        h = dA*h + (dtv*xv)*Bv;
        float part = h*Cv;
        part += __shfl_xor_sync(0xffffffffu, part, 1);
        part += __shfl_xor_sync(0xffffffffu, part, 2);
        part += __shfl_xor_sync(0xffffffffu, part, 4);
        part += __shfl_xor_sync(0xffffffffu, part, 8);
        if (n == 0) {
            float z = xzb[l*(2*DI)];
            float sig = 1.f / (1.f + __expf(-z));
            yb[l*DI] = (part + xv*Dval) * (z * sig);
        }
    }
}

// --------------- fp32 NT GEMM: C[m,n] = dot(A[m,:K], W[n,:K]) ---------------
// 128x128 block, BK=8, 8x8 per thread, 256 threads. epi==1: softplus(x+bias)
__global__ __launch_bounds__(256) void gemm_nt(
    const float* __restrict__ A, int lda,
    const float* __restrict__ W, int ldw,
    float* __restrict__ C, int ldc,
    int N, int K, int epi, const float* __restrict__ bias)
{
    __shared__ float As[8][132];
    __shared__ float Ws[8][132];
    const int tid = threadIdx.x;
    const int bm = blockIdx.y * 128;
    const int bn = blockIdx.x * 128;
    const int tx = tid & 15;
    const int ty = tid >> 4;
    const int lrow = tid >> 1;
    const int lkv  = (tid & 1) << 2;
    float acc[8][8];
#pragma unroll
    for (int i = 0; i < 8; i++)
#pragma unroll
        for (int j = 0; j < 8; j++) acc[i][j] = 0.f;

    const float* Ap = A + (size_t)(bm + lrow)*lda + lkv;
    const bool wv = (bn + lrow) < N;
    const float* Wp = W + (size_t)(wv ? (bn + lrow) : 0)*ldw + lkv;

    for (int k0 = 0; k0 < K; k0 += 8) {
        float4 a4 = *(const float4*)(Ap + k0);
        float4 w4 = wv ? *(const float4*)(Wp + k0) : make_float4(0.f,0.f,0.f,0.f);
        __syncthreads();
        As[lkv+0][lrow] = a4.x; As[lkv+1][lrow] = a4.y;
        As[lkv+2][lrow] = a4.z; As[lkv+3][lrow] = a4.w;
        Ws[lkv+0][lrow] = w4.x; Ws[lkv+1][lrow] = w4.y;
        Ws[lkv+2][lrow] = w4.z; Ws[lkv+3][lrow] = w4.w;
        __syncthreads();
#pragma unroll
        for (int kk = 0; kk < 8; kk++) {
            float a[8], bfr[8];
#pragma unroll
            for (int i = 0; i < 8; i++) a[i]   = As[kk][ty*8 + i];
#pragma unroll
            for (int j = 0; j < 8; j++) bfr[j] = Ws[kk][tx*8 + j];
#pragma unroll
            for (int i = 0; i < 8; i++)
#pragma unroll
                for (int j = 0; j < 8; j++) acc[i][j] += a[i]*bfr[j];
        }
    }

#pragma unroll
    for (int i = 0; i < 8; i++) {
        int gm = bm + ty*8 + i;
#pragma unroll
        for (int j = 0; j < 8; j += 4) {
            int gn = bn + tx*8 + j;
            if (gn < N) {
                float tmp[4];
#pragma unroll
                for (int q = 0; q < 4; q++) {
                    float u = acc[i][j+q];
                    if (epi == 1) {
                        float x = u + bias[gn+q];
                        u = (x > 20.f) ? x : log1pf(__expf(x));
                    }
                    tmp[q] = u;
                }
                *(float4*)(&C[(size_t)gm*ldc + gn]) = *(float4*)tmp;
            }
        }
    }
}

// ------------------------------- driver --------------------------------------
extern "C" void kernel_launch(void* const* d_in, const int* in_sizes, int n_in,
                              void* d_out, int out_size)
{
    (void)in_sizes; (void)n_in; (void)out_size;
    const int*   ids   = (const int*)d_in[0];
    const int*   pos   = (const int*)d_in[1];
    const float* emb   = (const float*)d_in[2];
    const float* pemb  = (const float*)d_in[3];
    const float* normw = (const float*)d_in[4];
    const float* inw   = (const float*)d_in[5];
    const float* convw = (const float*)d_in[6];
    const float* convb = (const float*)d_in[7];
    const float* xpw   = (const float*)d_in[8];
    const float* dtw   = (const float*)d_in[9];
    const float* dtb   = (const float*)d_in[10];
    const float* Alog  = (const float*)d_in[11];
    const float* Dvec  = (const float*)d_in[12];
    const float* outw  = (const float*)d_in[13];
    const float* normf = (const float*)d_in[14];
    float* logits = (float*)d_out;

    float *hid, *res, *hs, *xz, *xc, *xd, *dtv, *y;
    cudaGetSymbolAddress((void**)&hid, g_hidden);
    cudaGetSymbolAddress((void**)&res, g_residual);
    cudaGetSymbolAddress((void**)&hs,  g_hs);
    cudaGetSymbolAddress((void**)&xz,  g_xz);
    cudaGetSymbolAddress((void**)&xc,  g_xconv);
    cudaGetSymbolAddress((void**)&xd,  g_xdbl);
    cudaGetSymbolAddress((void**)&dtv, g_dt);
    cudaGetSymbolAddress((void**)&y,   g_y);

    embed_kernel<<<(TOK*DM + 255)/256, 256>>>(ids, pos, emb, pemb, hid, res);

    for (int layer = 0; layer < NL; layer++) {
        addnorm_kernel<<<TOK, 256>>>(hid, res, normw + (size_t)layer*DM, hs);

        // xz = hs @ in_proj^T : M=2048, N=3072, K=768
        {
            dim3 g(2*DI/128, TOK/128);
            gemm_nt<<<g, 256>>>(hs, DM, inw + (size_t)layer*2*DI*DM, DM,
                                xz, 2*DI, 2*DI, DM, 0, nullptr);
        }
        conv_silu_kernel<<<(TOK*DI + 255)/256, 256>>>(
            xz, convw + (size_t)layer*DI*4, convb + (size_t)layer*DI, xc);

        // x_dbl = xconv @ x_proj^T : M=2048, N=80, K=1536
        {
            dim3 g(1, TOK/128);
            gemm_nt<<<g, 256>>>(xc, DI, xpw + (size_t)layer*XD*DI, DI,
                                xd, XD, XD, DI, 0, nullptr);
        }
        // dt = softplus(x_dbl[:, :48] @ dt_proj^T + dt_b) : M=2048, N=1536, K=48
        {
            dim3 g(DI/128, TOK/128);
            gemm_nt<<<g, 256>>>(xd, XD, dtw + (size_t)layer*DI*DTR, DTR,
                                dtv, DI, DI, DTR, 1, dtb + (size_t)layer*DI);
        }
        scan_kernel<<<(BB*DI)/16, 256>>>(xc, dtv, xd, xz,
                                         Alog + (size_t)layer*DI*DS,
                                         Dvec + (size_t)layer*DI, y);
        // hidden = y @ out_proj^T : M=2048, N=768, K=1536
        {
            dim3 g(DM/128, TOK/128);
            gemm_nt<<<g, 256>>>(y, DI, outw + (size_t)layer*DM*DI, DI,
                                hid, DM, DM, DI, 0, nullptr);
        }
    }

    addnorm_kernel<<<TOK, 256>>>(hid, res, normf, hs);

    // logits = hs[:, :384] @ emb^T : M=2048, N=32000, K=384
    {
        dim3 g(VOCAB_N/128, TOK/128);
        gemm_nt<<<g, 256>>>(hs, DM, emb, DE, logits, VOCAB_N, VOCAB_N, DE, 0, nullptr);
    }
}

// round 3
// speedup vs baseline: 1.3843x; 1.3843x over previous
#include <cuda_runtime.h>
#include <cuda_bf16.h>
#include <cstdint>

#define BB 2
#define LL 1024
#define DM 768
#define DI 1536
#define DS 16
#define DTR 48
#define XD 80            // DT_RANK + 2*D_STATE
#define NL 6
#define VOCAB_N 32000
#define DE 384
#define TOK (BB*LL)      // 2048

typedef __nv_bfloat16 bf16;

// ------------------------- scratch (no allocation allowed) -------------------
__device__ __align__(128) float g_hidden[TOK*DM];
__device__ __align__(128) float g_residual[TOK*DM];
__device__ __align__(128) float g_hs[TOK*DM];
__device__ __align__(128) float g_xz[TOK*2*DI];
__device__ __align__(128) float g_xconv[TOK*DI];
__device__ __align__(128) float g_xdbl[TOK*XD];
__device__ __align__(128) float g_dt[TOK*DI];
__device__ __align__(128) bf16  g_ab[TOK*3*DI];        // split3 activations (M x 3K), max K=1536
__device__ __align__(128) bf16  g_wb[VOCAB_N*3*DE];    // split3 weights (N x 3K), max 32000x(3*384)

// ------------------------- embed: concat(tok_emb, pos_emb), zero residual ----
__global__ void embed_kernel(const int* __restrict__ ids, const int* __restrict__ pos,
                             const float* __restrict__ emb, const float* __restrict__ pemb,
                             float* __restrict__ hidden, float* __restrict__ res)
{
    int idx = blockIdx.x * blockDim.x + threadIdx.x;
    if (idx >= TOK*DM) return;
    int t = idx / DM, c = idx % DM;
    float v;
    if (c < DE) v = emb[(size_t)ids[t]*DE + c];
    else        v = pemb[(size_t)pos[t]*DE + (c-DE)];
    hidden[idx] = v;
    res[idx] = 0.f;
}

// ---------------- split3 helpers: v -> hi,lo bf16 in x3 layouts --------------
// A-side row layout (stride 3K): [hi(0..K) | lo(0..K) | hi(0..K)]
// B-side row layout (stride 3K): [hi(0..K) | hi(0..K) | lo(0..K)]
// dot_{3K}(A,B) = sum hi_a*hi_b + lo_a*hi_b + hi_a*lo_b  (full 1st-order product)
__device__ __forceinline__ void splitA_write(bf16* row, int K, int k, float v)
{
    bf16 hi = __float2bfloat16(v);
    row[k] = hi;
    row[2*K + k] = hi;
    row[K + k] = __float2bfloat16(v - __bfloat162float(hi));
}
__device__ __forceinline__ void splitB_write(bf16* row, int K, int k, float v)
{
    bf16 hi = __float2bfloat16(v);
    row[k] = hi;
    row[K + k] = hi;
    row[2*K + k] = __float2bfloat16(v - __bfloat162float(hi));
}

__global__ void split3A_kernel(const float* __restrict__ src, int lda, int K, int total,
                               bf16* __restrict__ dst)
{
    int idx = blockIdx.x * blockDim.x + threadIdx.x;
    if (idx >= total) return;
    int m = idx / K, k = idx - m*K;
    splitA_write(dst + (size_t)m*(3*K), K, k, src[(size_t)m*lda + k]);
}
__global__ void split3B_kernel(const float* __restrict__ src, int lda, int K, int total,
                               bf16* __restrict__ dst)
{
    int idx = blockIdx.x * blockDim.x + threadIdx.x;
    if (idx >= total) return;
    int m = idx / K, k = idx - m*K;
    splitB_write(dst + (size_t)m*(3*K), K, k, src[(size_t)m*lda + k]);
}

// ---- fused: res += hidden ; out = rmsnorm(res)*w ; + split3A bf16 output ----
__global__ __launch_bounds__(256) void addnorm_kernel(
    const float* __restrict__ h, float* __restrict__ res,
    const float* __restrict__ w, float* __restrict__ out, bf16* __restrict__ outs)
{
    int t = blockIdx.x;
    const float* hp = h + (size_t)t*DM;
    float* rp = res + (size_t)t*DM;
    float v[3];
    float ss = 0.f;
#pragma unroll
    for (int q = 0; q < 3; q++) {
        int i = threadIdx.x + q*256;
        v[q] = hp[i] + rp[i];
        ss += v[q]*v[q];
    }
#pragma unroll
    for (int o = 16; o > 0; o >>= 1) ss += __shfl_xor_sync(0xffffffffu, ss, o);
    __shared__ float red[8];
    if ((threadIdx.x & 31) == 0) red[threadIdx.x >> 5] = ss;
    __syncthreads();
    float tot = 0.f;
#pragma unroll
    for (int q = 0; q < 8; q++) tot += red[q];
    float rstd = rsqrtf(tot * (1.f/(float)DM) + 1e-5f);
    bf16* orow = outs + (size_t)t*(3*DM);
#pragma unroll
    for (int q = 0; q < 3; q++) {
        int i = threadIdx.x + q*256;
        rp[i] = v[q];
        float u = v[q] * rstd * w[i];
        out[(size_t)t*DM + i] = u;
        splitA_write(orow, DM, i, u);
    }
}

// ---- depthwise causal conv (width 4) + bias + silu (+split3A output) -------
__global__ void conv_silu_kernel(const float* __restrict__ xz,
                                 const float* __restrict__ cw,
                                 const float* __restrict__ cb,
                                 float* __restrict__ out, bf16* __restrict__ outs)
{
    int idx = blockIdx.x * blockDim.x + threadIdx.x;
    if (idx >= TOK*DI) return;
    int d = idx % DI;
    int t = idx / DI;
    int l = t % LL;
    float acc = cb[d];
    const float* base = xz + (size_t)t*(2*DI) + d;
#pragma unroll
    for (int j = 0; j < 4; j++) {
        int ll = l - 3 + j;
        if (ll >= 0) acc += cw[d*4+j] * base[(j-3)*(2*DI)];
    }
    float v = acc / (1.f + __expf(-acc));   // silu
    out[idx] = v;
    splitA_write(outs + (size_t)t*(3*DI), DI, d, v);
}

// ---------------- selective scan: 16 lanes per (b,d) channel -----------------
// output y written directly as split3A bf16 (only out_proj GEMM consumes it)
__global__ __launch_bounds__(256) void scan_kernel(
    const float* __restrict__ xc, const float* __restrict__ dt,
    const float* __restrict__ xd, const float* __restrict__ xz,
    const float* __restrict__ A_log, const float* __restrict__ Dv,
    bf16* __restrict__ ys)
{
    int tid = threadIdx.x;
    int p = blockIdx.x * 16 + (tid >> 4);   // (b,d) pair
    int n = tid & 15;
    int b = p / DI;
    int d = p - b*DI;
    float A = -__expf(A_log[d*DS + n]);
    float Dval = Dv[d];
    float h = 0.f;
    const float* xcb = xc + (size_t)b*LL*DI + d;
    const float* dtb = dt + (size_t)b*LL*DI + d;
    const float* xdb = xd + (size_t)b*LL*XD + DTR + n;   // B at +0, C at +DS
    const float* xzb = xz + (size_t)b*LL*(2*DI) + DI + d;
    bf16* yb = ys + (size_t)b*LL*(3*DI);
#pragma unroll 4
    for (int l = 0; l < LL; l++) {
        float xv  = xcb[l*DI];
        float dtv = dtb[l*DI];
        float Bv  = xdb[l*XD];
        float Cv  = xdb[l*XD + DS];
        float dA  = __expf(dtv * A);
        h = dA*h + (dtv*xv)*Bv;
        float part = h*Cv;
        part += __shfl_xor_sync(0xffffffffu, part, 1);
        part += __shfl_xor_sync(0xffffffffu, part, 2);
        part += __shfl_xor_sync(0xffffffffu, part, 4);
        part += __shfl_xor_sync(0xffffffffu, part, 8);
        if (n == 0) {
            float z = xzb[l*(2*DI)];
            float sig = 1.f / (1.f + __expf(-z));
            float v = (part + xv*Dval) * (z * sig);
            splitA_write(yb + (size_t)l*(3*DI), DI, d, v);
        }
    }
}

// --------------------------- tensor-core GEMM --------------------------------
// C[m,n] = sum_k A[m,k] * B[n,k]   (A: M x K2 bf16 row-major, B: N x K2 bf16 row-major)
// block 128x128, BK=32, 8 warps (2M x 4N), warp tile 64x32, mma m16n8k16 bf16->f32
__device__ __forceinline__ void ldsm_x4(uint32_t* r, uint32_t addr){
    asm volatile("ldmatrix.sync.aligned.m8n8.x4.shared.b16 {%0,%1,%2,%3}, [%4];"
      : "=r"(r[0]),"=r"(r[1]),"=r"(r[2]),"=r"(r[3]) : "r"(addr));
}
__device__ __forceinline__ void mma_bf16(float* c, const uint32_t* a, const uint32_t* b){
    asm volatile("mma.sync.aligned.m16n8k16.row.col.f32.bf16.bf16.f32 "
      "{%0,%1,%2,%3}, {%4,%5,%6,%7}, {%8,%9}, {%0,%1,%2,%3};"
      : "+f"(c[0]),"+f"(c[1]),"+f"(c[2]),"+f"(c[3])
      : "r"(a[0]),"r"(a[1]),"r"(a[2]),"r"(a[3]), "r"(b[0]),"r"(b[1]));
}

__global__ __launch_bounds__(256) void gemm_mma(
    const bf16* __restrict__ A, const bf16* __restrict__ B,
    float* __restrict__ C, int N, int K2, int ldc)
{
    __shared__ __align__(16) bf16 sA[128*40];
    __shared__ __align__(16) bf16 sB[128*40];
    const int tid = threadIdx.x;
    const int lane = tid & 31, wid = tid >> 5;
    const int wm = wid & 1, wn = wid >> 1;
    const int bm = blockIdx.y * 128, bn = blockIdx.x * 128;

    const int lr = tid >> 2;         // 0..63
    const int lc = (tid & 3) * 8;    // half offset 0/8/16/24
    const bf16* Ap = A + (size_t)(bm + lr)*K2 + lc;
    const int br0 = bn + lr, br1 = bn + lr + 64;
    const bool bv0 = br0 < N, bv1 = br1 < N;
    const bf16* Bp0 = B + (size_t)(bv0 ? br0 : 0)*K2 + lc;
    const bf16* Bp1 = B + (size_t)(bv1 ? br1 : 0)*K2 + lc;

    float acc[4][4][4];
#pragma unroll
    for (int i = 0; i < 4; i++)
#pragma unroll
        for (int j = 0; j < 4; j++)
#pragma unroll
            for (int q = 0; q < 4; q++) acc[i][j][q] = 0.f;

    const uint4 z4 = make_uint4(0u,0u,0u,0u);
    uint4 pa0 = *(const uint4*)(Ap);
    uint4 pa1 = *(const uint4*)(Ap + (size_t)64*K2);
    uint4 pb0 = bv0 ? *(const uint4*)(Bp0) : z4;
    uint4 pb1 = bv1 ? *(const uint4*)(Bp1) : z4;

    uint32_t sAb = (uint32_t)__cvta_generic_to_shared(sA);
    uint32_t sBb = (uint32_t)__cvta_generic_to_shared(sB);
    const int ar  = lane & 15;                         // a-frag row within 16
    const int ak  = (lane >> 4) * 8;                   // a-frag k offset
    const int brr = (lane & 7) + ((lane >> 4) & 1)*8;  // b-frag row within 16
    const int bk  = ((lane >> 3) & 1) * 8;             // b-frag k offset

    for (int k0 = 0; k0 < K2; k0 += 32) {
        __syncthreads();
        *(uint4*)(sA + lr*40 + lc)        = pa0;
        *(uint4*)(sA + (lr+64)*40 + lc)   = pa1;
        *(uint4*)(sB + lr*40 + lc)        = pb0;
        *(uint4*)(sB + (lr+64)*40 + lc)   = pb1;
        __syncthreads();
        int kn = k0 + 32;
        if (kn < K2) {
            pa0 = *(const uint4*)(Ap + kn);
            pa1 = *(const uint4*)(Ap + (size_t)64*K2 + kn);
            pb0 = bv0 ? *(const uint4*)(Bp0 + kn) : z4;
            pb1 = bv1 ? *(const uint4*)(Bp1 + kn) : z4;
        }
#pragma unroll
        for (int kk = 0; kk < 2; kk++) {
            uint32_t afr[4][4], bfr[4][2];
#pragma unroll
            for (int mi = 0; mi < 4; mi++) {
                int row = wm*64 + mi*16 + ar;
                ldsm_x4(afr[mi], sAb + (uint32_t)(row*40 + kk*16 + ak)*2);
            }
#pragma unroll
            for (int np = 0; np < 2; np++) {
                int row = wn*32 + np*16 + brr;
                uint32_t q[4];
                ldsm_x4(q, sBb + (uint32_t)(row*40 + kk*16 + bk)*2);
                bfr[np*2+0][0]=q[0]; bfr[np*2+0][1]=q[1];
                bfr[np*2+1][0]=q[2]; bfr[np*2+1][1]=q[3];
            }
#pragma unroll
            for (int mi = 0; mi < 4; mi++)
#pragma unroll
                for (int ni = 0; ni < 4; ni++)
                    mma_bf16(acc[mi][ni], afr[mi], bfr[ni]);
        }
    }

    const int grp = lane >> 2, qd = lane & 3;
#pragma unroll
    for (int mi = 0; mi < 4; mi++) {
        int m = bm + wm*64 + mi*16 + grp;
#pragma unroll
        for (int ni = 0; ni < 4; ni++) {
            int n = bn + wn*32 + ni*8 + qd*2;
            if (n < N) {
                *(float2*)(&C[(size_t)m*ldc + n])     = make_float2(acc[mi][ni][0], acc[mi][ni][1]);
                *(float2*)(&C[(size_t)(m+8)*ldc + n]) = make_float2(acc[mi][ni][2], acc[mi][ni][3]);
            }
        }
    }
}

// --------------- fp32 NT GEMM (dt projection only: N=1536, K=48) -------------
__global__ __launch_bounds__(256) void gemm_nt(
    const float* __restrict__ A, int lda,
    const float* __restrict__ W, int ldw,
    float* __restrict__ C, int ldc,
    int N, int K, int epi, const float* __restrict__ bias)
{
    __shared__ float As[8][132];
    __shared__ float Ws[8][132];
    const int tid = threadIdx.x;
    const int bm = blockIdx.y * 128;
    const int bn = blockIdx.x * 128;
    const int tx = tid & 15;
    const int ty = tid >> 4;
    const int lrow = tid >> 1;
    const int lkv  = (tid & 1) << 2;
    float acc[8][8];
#pragma unroll
    for (int i = 0; i < 8; i++)
#pragma unroll
        for (int j = 0; j < 8; j++) acc[i][j] = 0.f;

    const float* Ap = A + (size_t)(bm + lrow)*lda + lkv;
    const bool wv = (bn + lrow) < N;
    const float* Wp = W + (size_t)(wv ? (bn + lrow) : 0)*ldw + lkv;

    for (int k0 = 0; k0 < K; k0 += 8) {
        float4 a4 = *(const float4*)(Ap + k0);
        float4 w4 = wv ? *(const float4*)(Wp + k0) : make_float4(0.f,0.f,0.f,0.f);
        __syncthreads();
        As[lkv+0][lrow] = a4.x; As[lkv+1][lrow] = a4.y;
        As[lkv+2][lrow] = a4.z; As[lkv+3][lrow] = a4.w;
        Ws[lkv+0][lrow] = w4.x; Ws[lkv+1][lrow] = w4.y;
        Ws[lkv+2][lrow] = w4.z; Ws[lkv+3][lrow] = w4.w;
        __syncthreads();
#pragma unroll
        for (int kk = 0; kk < 8; kk++) {
            float a[8], bfr[8];
#pragma unroll
            for (int i = 0; i < 8; i++) a[i]   = As[kk][ty*8 + i];
#pragma unroll
            for (int j = 0; j < 8; j++) bfr[j] = Ws[kk][tx*8 + j];
#pragma unroll
            for (int i = 0; i < 8; i++)
#pragma unroll
                for (int j = 0; j < 8; j++) acc[i][j] += a[i]*bfr[j];
        }
    }

#pragma unroll
    for (int i = 0; i < 8; i++) {
        int gm = bm + ty*8 + i;
#pragma unroll
        for (int j = 0; j < 8; j += 4) {
            int gn = bn + tx*8 + j;
            if (gn < N) {
                float tmp[4];
#pragma unroll
                for (int q = 0; q < 4; q++) {
                    float u = acc[i][j+q];
                    if (epi == 1) {
                        float x = u + bias[gn+q];
                        u = (x > 20.f) ? x : log1pf(__expf(x));
                    }
                    tmp[q] = u;
                }
                *(float4*)(&C[(size_t)gm*ldc + gn]) = *(float4*)tmp;
            }
        }
    }
}

// ------------------------------- driver --------------------------------------
extern "C" void kernel_launch(void* const* d_in, const int* in_sizes, int n_in,
                              void* d_out, int out_size)
{
    (void)in_sizes; (void)n_in; (void)out_size;
    const int*   ids   = (const int*)d_in[0];
    const int*   pos   = (const int*)d_in[1];
    const float* emb   = (const float*)d_in[2];
    const float* pemb  = (const float*)d_in[3];
    const float* normw = (const float*)d_in[4];
    const float* inw   = (const float*)d_in[5];
    const float* convw = (const float*)d_in[6];
    const float* convb = (const float*)d_in[7];
    const float* xpw   = (const float*)d_in[8];
    const float* dtw   = (const float*)d_in[9];
    const float* dtb   = (const float*)d_in[10];
    const float* Alog  = (const float*)d_in[11];
    const float* Dvec  = (const float*)d_in[12];
    const float* outw  = (const float*)d_in[13];
    const float* normf = (const float*)d_in[14];
    float* logits = (float*)d_out;

    float *hid, *res, *hs, *xz, *xc, *xd, *dtv;
    bf16 *ab, *wb;
    cudaGetSymbolAddress((void**)&hid, g_hidden);
    cudaGetSymbolAddress((void**)&res, g_residual);
    cudaGetSymbolAddress((void**)&hs,  g_hs);
    cudaGetSymbolAddress((void**)&xz,  g_xz);
    cudaGetSymbolAddress((void**)&xc,  g_xconv);
    cudaGetSymbolAddress((void**)&xd,  g_xdbl);
    cudaGetSymbolAddress((void**)&dtv, g_dt);
    cudaGetSymbolAddress((void**)&ab,  g_ab);
    cudaGetSymbolAddress((void**)&wb,  g_wb);

    embed_kernel<<<(TOK*DM + 255)/256, 256>>>(ids, pos, emb, pemb, hid, res);

    for (int layer = 0; layer < NL; layer++) {
        // res += hid; hs = rmsnorm(res); ab = split3A(hs) (stride 3*DM)
        addnorm_kernel<<<TOK, 256>>>(hid, res, normw + (size_t)layer*DM, hs, ab);

        // xz = hs @ in_proj^T : M=2048, N=3072, K=768 (K3=2304)
        split3B_kernel<<<(2*DI*DM + 255)/256, 256>>>(inw + (size_t)layer*2*DI*DM, DM, DM, 2*DI*DM, wb);
        { dim3 g(2*DI/128, TOK/128);
          gemm_mma<<<g, 256>>>(ab, wb, xz, 2*DI, 3*DM, 2*DI); }

        // xc = silu(conv(x)) ; ab = split3A(xc) (stride 3*DI)
        conv_silu_kernel<<<(TOK*DI + 255)/256, 256>>>(
            xz, convw + (size_t)layer*DI*4, convb + (size_t)layer*DI, xc, ab);

        // x_dbl = xc @ x_proj^T : N=80, K=1536 (K3=4608)
        split3B_kernel<<<(XD*DI + 255)/256, 256>>>(xpw + (size_t)layer*XD*DI, DI, DI, XD*DI, wb);
        { dim3 g(1, TOK/128);
          gemm_mma<<<g, 256>>>(ab, wb, xd, XD, 3*DI, XD); }

        // dt = softplus(x_dbl[:, :48] @ dt_proj^T + dtb) : fp32 (N=1536, K=48)
        { dim3 g(DI/128, TOK/128);
          gemm_nt<<<g, 256>>>(xd, XD, dtw + (size_t)layer*DI*DTR, DTR,
                              dtv, DI, DI, DTR, 1, dtb + (size_t)layer*DI); }

        // selective scan -> ab = split3A(y) (stride 3*DI)
        scan_kernel<<<(BB*DI)/16, 256>>>(xc, dtv, xd, xz,
                                         Alog + (size_t)layer*DI*DS,
                                         Dvec + (size_t)layer*DI, ab);

        // hid = y @ out_proj^T : N=768, K=1536 (K3=4608)
        split3B_kernel<<<(DM*DI + 255)/256, 256>>>(outw + (size_t)layer*DM*DI, DI, DI, DM*DI, wb);
        { dim3 g(DM/128, TOK/128);
          gemm_mma<<<g, 256>>>(ab, wb, hid, DM, 3*DI, DM); }
    }

    addnorm_kernel<<<TOK, 256>>>(hid, res, normf, hs, ab);

    // logits = hs[:, :384] @ emb^T : N=32000, K=384 (K3=1152)
    split3A_kernel<<<(TOK*DE + 255)/256, 256>>>(hs, DM, DE, TOK*DE, ab);
    split3B_kernel<<<(VOCAB_N*DE + 255)/256, 256>>>(emb, DE, DE, VOCAB_N*DE, wb);
    { dim3 g(VOCAB_N/128, TOK/128);
      gemm_mma<<<g, 256>>>(ab, wb, logits, VOCAB_N, 3*DE, VOCAB_N); }
}

// round 4
// speedup vs baseline: 1.4993x; 1.0831x over previous
#include <cuda_runtime.h>
#include <cuda_bf16.h>
#include <cstdint>

#define BB 2
#define LL 1024
#define DM 768
#define DI 1536
#define DS 16
#define DTR 48
#define XD 80            // DT_RANK + 2*D_STATE
#define NL 6
#define VOCAB_N 32000
#define DE 384
#define TOK (BB*LL)      // 2048

typedef __nv_bfloat16 bf16;

// ------------------------- scratch (no allocation allowed) -------------------
__device__ __align__(128) float g_hidden[TOK*DM];
__device__ __align__(128) float g_residual[TOK*DM];
__device__ __align__(128) float g_hs[TOK*DM];
__device__ __align__(128) float g_xz[TOK*2*DI];
__device__ __align__(128) float g_xconv[TOK*DI];
__device__ __align__(128) float g_xdbl[TOK*XD];
__device__ __align__(128) float g_dt[TOK*DI];
__device__ __align__(128) bf16  g_ab[TOK*3*DI];        // split3 activations (M x 3K), max K=1536
__device__ __align__(128) bf16  g_wb[VOCAB_N*3*DE];    // split3 weights (N x 3K)

// ------------------------- embed: concat(tok_emb, pos_emb), zero residual ----
__global__ void embed_kernel(const int* __restrict__ ids, const int* __restrict__ pos,
                             const float* __restrict__ emb, const float* __restrict__ pemb,
                             float* __restrict__ hidden, float* __restrict__ res)
{
    int idx = blockIdx.x * blockDim.x + threadIdx.x;
    if (idx >= TOK*DM) return;
    int t = idx / DM, c = idx % DM;
    float v;
    if (c < DE) v = emb[(size_t)ids[t]*DE + c];
    else        v = pemb[(size_t)pos[t]*DE + (c-DE)];
    hidden[idx] = v;
    res[idx] = 0.f;
}

__global__ void zero_kernel(float* __restrict__ p, int n)
{
    int i = blockIdx.x * blockDim.x + threadIdx.x;
    if (i < n) p[i] = 0.f;
}

// ---------------- split3 helpers: v -> hi,lo bf16 in x3 layouts --------------
// A-side row layout (stride 3K): [hi | lo | hi]
// B-side row layout (stride 3K): [hi | hi | lo]
// dot = hi_a*hi_b + lo_a*hi_b + hi_a*lo_b
__device__ __forceinline__ void splitA_write(bf16* row, int K, int k, float v)
{
    bf16 hi = __float2bfloat16(v);
    row[k] = hi;
    row[2*K + k] = hi;
    row[K + k] = __float2bfloat16(v - __bfloat162float(hi));
}
__device__ __forceinline__ void splitB_write(bf16* row, int K, int k, float v)
{
    bf16 hi = __float2bfloat16(v);
    row[k] = hi;
    row[K + k] = hi;
    row[2*K + k] = __float2bfloat16(v - __bfloat162float(hi));
}

__global__ void split3A_kernel(const float* __restrict__ src, int lda, int K, int total,
                               bf16* __restrict__ dst)
{
    int idx = blockIdx.x * blockDim.x + threadIdx.x;
    if (idx >= total) return;
    int m = idx / K, k = idx - m*K;
    splitA_write(dst + (size_t)m*(3*K), K, k, src[(size_t)m*lda + k]);
}
__global__ void split3B_kernel(const float* __restrict__ src, int lda, int K, int total,
                               bf16* __restrict__ dst)
{
    int idx = blockIdx.x * blockDim.x + threadIdx.x;
    if (idx >= total) return;
    int m = idx / K, k = idx - m*K;
    splitB_write(dst + (size_t)m*(3*K), K, k, src[(size_t)m*lda + k]);
}

// ---- fused: res += hidden ; out = rmsnorm(res)*w ; + split3A bf16 output ----
__global__ __launch_bounds__(256) void addnorm_kernel(
    const float* __restrict__ h, float* __restrict__ res,
    const float* __restrict__ w, float* __restrict__ out, bf16* __restrict__ outs)
{
    int t = blockIdx.x;
    const float* hp = h + (size_t)t*DM;
    float* rp = res + (size_t)t*DM;
    float v[3];
    float ss = 0.f;
#pragma unroll
    for (int q = 0; q < 3; q++) {
        int i = threadIdx.x + q*256;
        v[q] = hp[i] + rp[i];
        ss += v[q]*v[q];
    }
#pragma unroll
    for (int o = 16; o > 0; o >>= 1) ss += __shfl_xor_sync(0xffffffffu, ss, o);
    __shared__ float red[8];
    if ((threadIdx.x & 31) == 0) red[threadIdx.x >> 5] = ss;
    __syncthreads();
    float tot = 0.f;
#pragma unroll
    for (int q = 0; q < 8; q++) tot += red[q];
    float rstd = rsqrtf(tot * (1.f/(float)DM) + 1e-5f);
    bf16* orow = outs + (size_t)t*(3*DM);
#pragma unroll
    for (int q = 0; q < 3; q++) {
        int i = threadIdx.x + q*256;
        rp[i] = v[q];
        float u = v[q] * rstd * w[i];
        out[(size_t)t*DM + i] = u;
        splitA_write(orow, DM, i, u);
    }
}

// ---- depthwise causal conv (width 4) + bias + silu (+split3A output) -------
__global__ void conv_silu_kernel(const float* __restrict__ xz,
                                 const float* __restrict__ cw,
                                 const float* __restrict__ cb,
                                 float* __restrict__ out, bf16* __restrict__ outs)
{
    int idx = blockIdx.x * blockDim.x + threadIdx.x;
    if (idx >= TOK*DI) return;
    int d = idx % DI;
    int t = idx / DI;
    int l = t % LL;
    float acc = cb[d];
    const float* base = xz + (size_t)t*(2*DI) + d;
#pragma unroll
    for (int j = 0; j < 4; j++) {
        int ll = l - 3 + j;
        if (ll >= 0) acc += cw[d*4+j] * base[(j-3)*(2*DI)];
    }
    float v = acc / (1.f + __expf(-acc));   // silu
    out[idx] = v;
    splitA_write(outs + (size_t)t*(3*DI), DI, d, v);
}

// ---------------- selective scan: 16 lanes per (b,d) channel -----------------
__global__ __launch_bounds__(256) void scan_kernel(
    const float* __restrict__ xc, const float* __restrict__ dt,
    const float* __restrict__ xd, const float* __restrict__ xz,
    const float* __restrict__ A_log, const float* __restrict__ Dv,
    bf16* __restrict__ ys)
{
    int tid = threadIdx.x;
    int p = blockIdx.x * 16 + (tid >> 4);   // (b,d) pair
    int n = tid & 15;
    int b = p / DI;
    int d = p - b*DI;
    float A = -__expf(A_log[d*DS + n]);
    float Dval = Dv[d];
    float h = 0.f;
    const float* xcb = xc + (size_t)b*LL*DI + d;
    const float* dtb = dt + (size_t)b*LL*DI + d;
    const float* xdb = xd + (size_t)b*LL*XD + DTR + n;
    const float* xzb = xz + (size_t)b*LL*(2*DI) + DI + d;
    bf16* yb = ys + (size_t)b*LL*(3*DI);
#pragma unroll 4
    for (int l = 0; l < LL; l++) {
        float xv  = xcb[l*DI];
        float dtv = dtb[l*DI];
        float Bv  = xdb[l*XD];
        float Cv  = xdb[l*XD + DS];
        float dA  = __expf(dtv * A);
        h = dA*h + (dtv*xv)*Bv;
        float part = h*Cv;
        part += __shfl_xor_sync(0xffffffffu, part, 1);
        part += __shfl_xor_sync(0xffffffffu, part, 2);
        part += __shfl_xor_sync(0xffffffffu, part, 4);
        part += __shfl_xor_sync(0xffffffffu, part, 8);
        if (n == 0) {
            float z = xzb[l*(2*DI)];
            float sig = 1.f / (1.f + __expf(-z));
            float v = (part + xv*Dval) * (z * sig);
            splitA_write(yb + (size_t)l*(3*DI), DI, d, v);
        }
    }
}

// --------------------------- tensor-core GEMM --------------------------------
// C[m,n] = sum_k A[m,k]*B[n,k]. 128x128 block, BK=32, cp.async double-buffered.
// grid.z = ksplit (contiguous K chunks); atomic=1 -> fp32 atomicAdd epilogue.
__device__ __forceinline__ void ldsm_x4(uint32_t* r, uint32_t addr){
    asm volatile("ldmatrix.sync.aligned.m8n8.x4.shared.b16 {%0,%1,%2,%3}, [%4];"
      : "=r"(r[0]),"=r"(r[1]),"=r"(r[2]),"=r"(r[3]) : "r"(addr));
}
__device__ __forceinline__ void mma_bf16(float* c, const uint32_t* a, const uint32_t* b){
    asm volatile("mma.sync.aligned.m16n8k16.row.col.f32.bf16.bf16.f32 "
      "{%0,%1,%2,%3}, {%4,%5,%6,%7}, {%8,%9}, {%0,%1,%2,%3};"
      : "+f"(c[0]),"+f"(c[1]),"+f"(c[2]),"+f"(c[3])
      : "r"(a[0]),"r"(a[1]),"r"(a[2]),"r"(a[3]), "r"(b[0]),"r"(b[1]));
}
__device__ __forceinline__ void cp8(uint32_t daddr, const void* gptr, uint32_t srcsz){
    asm volatile("cp.async.ca.shared.global [%0], [%1], 8, %2;\n"
      :: "r"(daddr), "l"(gptr), "r"(srcsz));
}

#define SSTRIDE 40
#define STG_HALF (128*SSTRIDE)

__global__ __launch_bounds__(256,2) void gemm_mma(
    const bf16* __restrict__ A, const bf16* __restrict__ B,
    float* __restrict__ C, int N, int K2, int ldc, int katomic)
{
    __shared__ __align__(16) bf16 sA[2*STG_HALF];
    __shared__ __align__(16) bf16 sB[2*STG_HALF];
    const int tid = threadIdx.x;
    const int lane = tid & 31, wid = tid >> 5;
    const int wm = wid & 1, wn = wid >> 1;
    const int bm = blockIdx.y * 128, bn = blockIdx.x * 128;

    const int ksplit = gridDim.z;
    const int iters_total = K2 / 32;
    const int per = iters_total / ksplit;
    const int kbeg = blockIdx.z * per * 32;
    const int iters = per;

    // cp.async chunk mapping: 4 chunks of 8B per matrix per thread
    int crow[4], ccol[4];
#pragma unroll
    for (int q = 0; q < 4; q++) {
        int c = tid + q*256;
        crow[q] = c >> 3;
        ccol[q] = (c & 7) * 4;
    }

    uint32_t sAb = (uint32_t)__cvta_generic_to_shared(sA);
    uint32_t sBb = (uint32_t)__cvta_generic_to_shared(sB);

    float acc[4][4][4];
#pragma unroll
    for (int i = 0; i < 4; i++)
#pragma unroll
        for (int j = 0; j < 4; j++)
#pragma unroll
            for (int q = 0; q < 4; q++) acc[i][j][q] = 0.f;

    // prologue: stage 0
    {
        int k = kbeg;
#pragma unroll
        for (int q = 0; q < 4; q++) {
            int row = crow[q], col = ccol[q];
            cp8(sAb + (uint32_t)(row*SSTRIDE + col)*2,
                A + (size_t)(bm + row)*K2 + k + col, 8u);
            int brow = bn + row;
            bool v = brow < N;
            cp8(sBb + (uint32_t)(row*SSTRIDE + col)*2,
                B + (size_t)(v ? brow : 0)*K2 + k + col, v ? 8u : 0u);
        }
        asm volatile("cp.async.commit_group;\n" ::: "memory");
    }

    const int ar  = lane & 15;
    const int ak  = (lane >> 4) * 8;
    const int brr = (lane & 7) + ((lane >> 4) & 1)*8;
    const int bk  = ((lane >> 3) & 1) * 8;

    int buf = 0;
    for (int it = 0; it < iters; it++) {
        asm volatile("cp.async.wait_group 0;\n" ::: "memory");
        __syncthreads();
        if (it + 1 < iters) {
            int k = kbeg + (it+1)*32;
            uint32_t so = (uint32_t)(buf ^ 1) * (STG_HALF*2);
#pragma unroll
            for (int q = 0; q < 4; q++) {
                int row = crow[q], col = ccol[q];
                cp8(sAb + so + (uint32_t)(row*SSTRIDE + col)*2,
                    A + (size_t)(bm + row)*K2 + k + col, 8u);
                int brow = bn + row;
                bool v = brow < N;
                cp8(sBb + so + (uint32_t)(row*SSTRIDE + col)*2,
                    B + (size_t)(v ? brow : 0)*K2 + k + col, v ? 8u : 0u);
            }
            asm volatile("cp.async.commit_group;\n" ::: "memory");
        }
        uint32_t sAc = sAb + (uint32_t)buf * (STG_HALF*2);
        uint32_t sBc = sBb + (uint32_t)buf * (STG_HALF*2);
#pragma unroll
        for (int kk = 0; kk < 2; kk++) {
            uint32_t afr[4][4], bfr[4][2];
#pragma unroll
            for (int mi = 0; mi < 4; mi++) {
                int row = wm*64 + mi*16 + ar;
                ldsm_x4(afr[mi], sAc + (uint32_t)(row*SSTRIDE + kk*16 + ak)*2);
            }
#pragma unroll
            for (int np = 0; np < 2; np++) {
                int row = wn*32 + np*16 + brr;
                uint32_t q4[4];
                ldsm_x4(q4, sBc + (uint32_t)(row*SSTRIDE + kk*16 + bk)*2);
                bfr[np*2+0][0]=q4[0]; bfr[np*2+0][1]=q4[1];
                bfr[np*2+1][0]=q4[2]; bfr[np*2+1][1]=q4[3];
            }
#pragma unroll
            for (int mi = 0; mi < 4; mi++)
#pragma unroll
                for (int ni = 0; ni < 4; ni++)
                    mma_bf16(acc[mi][ni], afr[mi], bfr[ni]);
        }
        buf ^= 1;
    }

    const int grp = lane >> 2, qd = lane & 3;
#pragma unroll
    for (int mi = 0; mi < 4; mi++) {
        int m = bm + wm*64 + mi*16 + grp;
#pragma unroll
        for (int ni = 0; ni < 4; ni++) {
            int n = bn + wn*32 + ni*8 + qd*2;
            if (n < N) {
                if (katomic) {
                    atomicAdd(&C[(size_t)m*ldc + n],       acc[mi][ni][0]);
                    if (n+1 < N) atomicAdd(&C[(size_t)m*ldc + n+1], acc[mi][ni][1]);
                    atomicAdd(&C[(size_t)(m+8)*ldc + n],   acc[mi][ni][2]);
                    if (n+1 < N) atomicAdd(&C[(size_t)(m+8)*ldc + n+1], acc[mi][ni][3]);
                } else {
                    *(float2*)(&C[(size_t)m*ldc + n])     = make_float2(acc[mi][ni][0], acc[mi][ni][1]);
                    *(float2*)(&C[(size_t)(m+8)*ldc + n]) = make_float2(acc[mi][ni][2], acc[mi][ni][3]);
                }
            }
        }
    }
}

// --------------- fp32 NT GEMM (dt projection only: N=1536, K=48) -------------
__global__ __launch_bounds__(256) void gemm_nt(
    const float* __restrict__ A, int lda,
    const float* __restrict__ W, int ldw,
    float* __restrict__ C, int ldc,
    int N, int K, int epi, const float* __restrict__ bias)
{
    __shared__ float As[8][132];
    __shared__ float Ws[8][132];
    const int tid = threadIdx.x;
    const int bm = blockIdx.y * 128;
    const int bn = blockIdx.x * 128;
    const int tx = tid & 15;
    const int ty = tid >> 4;
    const int lrow = tid >> 1;
    const int lkv  = (tid & 1) << 2;
    float acc[8][8];
#pragma unroll
    for (int i = 0; i < 8; i++)
#pragma unroll
        for (int j = 0; j < 8; j++) acc[i][j] = 0.f;

    const float* Ap = A + (size_t)(bm + lrow)*lda + lkv;
    const bool wv = (bn + lrow) < N;
    const float* Wp = W + (size_t)(wv ? (bn + lrow) : 0)*ldw + lkv;

    for (int k0 = 0; k0 < K; k0 += 8) {
        float4 a4 = *(const float4*)(Ap + k0);
        float4 w4 = wv ? *(const float4*)(Wp + k0) : make_float4(0.f,0.f,0.f,0.f);
        __syncthreads();
        As[lkv+0][lrow] = a4.x; As[lkv+1][lrow] = a4.y;
        As[lkv+2][lrow] = a4.z; As[lkv+3][lrow] = a4.w;
        Ws[lkv+0][lrow] = w4.x; Ws[lkv+1][lrow] = w4.y;
        Ws[lkv+2][lrow] = w4.z; Ws[lkv+3][lrow] = w4.w;
        __syncthreads();
#pragma unroll
        for (int kk = 0; kk < 8; kk++) {
            float a[8], bfr[8];
#pragma unroll
            for (int i = 0; i < 8; i++) a[i]   = As[kk][ty*8 + i];
#pragma unroll
            for (int j = 0; j < 8; j++) bfr[j] = Ws[kk][tx*8 + j];
#pragma unroll
            for (int i = 0; i < 8; i++)
#pragma unroll
                for (int j = 0; j < 8; j++) acc[i][j] += a[i]*bfr[j];
        }
    }

#pragma unroll
    for (int i = 0; i < 8; i++) {
        int gm = bm + ty*8 + i;
#pragma unroll
        for (int j = 0; j < 8; j += 4) {
            int gn = bn + tx*8 + j;
            if (gn < N) {
                float tmp[4];
#pragma unroll
                for (int q = 0; q < 4; q++) {
                    float u = acc[i][j+q];
                    if (epi == 1) {
                        float x = u + bias[gn+q];
                        u = (x > 20.f) ? x : log1pf(__expf(x));
                    }
                    tmp[q] = u;
                }
                *(float4*)(&C[(size_t)gm*ldc + gn]) = *(float4*)tmp;
            }
        }
    }
}

// ------------------------------- driver --------------------------------------
extern "C" void kernel_launch(void* const* d_in, const int* in_sizes, int n_in,
                              void* d_out, int out_size)
{
    (void)in_sizes; (void)n_in; (void)out_size;
    const int*   ids   = (const int*)d_in[0];
    const int*   pos   = (const int*)d_in[1];
    const float* emb   = (const float*)d_in[2];
    const float* pemb  = (const float*)d_in[3];
    const float* normw = (const float*)d_in[4];
    const float* inw   = (const float*)d_in[5];
    const float* convw = (const float*)d_in[6];
    const float* convb = (const float*)d_in[7];
    const float* xpw   = (const float*)d_in[8];
    const float* dtw   = (const float*)d_in[9];
    const float* dtb   = (const float*)d_in[10];
    const float* Alog  = (const float*)d_in[11];
    const float* Dvec  = (const float*)d_in[12];
    const float* outw  = (const float*)d_in[13];
    const float* normf = (const float*)d_in[14];
    float* logits = (float*)d_out;

    float *hid, *res, *hs, *xz, *xc, *xd, *dtv;
    bf16 *ab, *wb;
    cudaGetSymbolAddress((void**)&hid, g_hidden);
    cudaGetSymbolAddress((void**)&res, g_residual);
    cudaGetSymbolAddress((void**)&hs,  g_hs);
    cudaGetSymbolAddress((void**)&xz,  g_xz);
    cudaGetSymbolAddress((void**)&xc,  g_xconv);
    cudaGetSymbolAddress((void**)&xd,  g_xdbl);
    cudaGetSymbolAddress((void**)&dtv, g_dt);
    cudaGetSymbolAddress((void**)&ab,  g_ab);
    cudaGetSymbolAddress((void**)&wb,  g_wb);

    embed_kernel<<<(TOK*DM + 255)/256, 256>>>(ids, pos, emb, pemb, hid, res);

    for (int layer = 0; layer < NL; layer++) {
        addnorm_kernel<<<TOK, 256>>>(hid, res, normw + (size_t)layer*DM, hs, ab);

        // xz = hs @ in_proj^T : N=3072, K3=2304
        split3B_kernel<<<(2*DI*DM + 255)/256, 256>>>(inw + (size_t)layer*2*DI*DM, DM, DM, 2*DI*DM, wb);
        { dim3 g(2*DI/128, TOK/128, 1);
          gemm_mma<<<g, 256>>>(ab, wb, xz, 2*DI, 3*DM, 2*DI, 0); }

        conv_silu_kernel<<<(TOK*DI + 255)/256, 256>>>(
            xz, convw + (size_t)layer*DI*4, convb + (size_t)layer*DI, xc, ab);

        // x_dbl = xc @ x_proj^T : N=80, K3=4608, split-K=8 (144 iters /8 = 18)
        split3B_kernel<<<(XD*DI + 255)/256, 256>>>(xpw + (size_t)layer*XD*DI, DI, DI, XD*DI, wb);
        zero_kernel<<<(TOK*XD + 255)/256, 256>>>(xd, TOK*XD);
        { dim3 g(1, TOK/128, 8);
          gemm_mma<<<g, 256>>>(ab, wb, xd, XD, 3*DI, XD, 1); }

        // dt = softplus(x_dbl[:, :48] @ dt_proj^T + dtb) : fp32
        { dim3 g(DI/128, TOK/128);
          gemm_nt<<<g, 256>>>(xd, XD, dtw + (size_t)layer*DI*DTR, DTR,
                              dtv, DI, DI, DTR, 1, dtb + (size_t)layer*DI); }

        scan_kernel<<<(BB*DI)/16, 256>>>(xc, dtv, xd, xz,
                                         Alog + (size_t)layer*DI*DS,
                                         Dvec + (size_t)layer*DI, ab);

        // hid = y @ out_proj^T : N=768, K3=4608, split-K=3 (144/3 = 48)
        split3B_kernel<<<(DM*DI + 255)/256, 256>>>(outw + (size_t)layer*DM*DI, DI, DI, DM*DI, wb);
        zero_kernel<<<(TOK*DM + 255)/256, 256>>>(hid, TOK*DM);
        { dim3 g(DM/128, TOK/128, 3);
          gemm_mma<<<g, 256>>>(ab, wb, hid, DM, 3*DI, DM, 1); }
    }

    addnorm_kernel<<<TOK, 256>>>(hid, res, normf, hs, ab);

    // logits = hs[:, :384] @ emb^T : N=32000, K3=1152
    split3A_kernel<<<(TOK*DE + 255)/256, 256>>>(hs, DM, DE, TOK*DE, ab);
    split3B_kernel<<<(VOCAB_N*DE + 255)/256, 256>>>(emb, DE, DE, VOCAB_N*DE, wb);
    { dim3 g(VOCAB_N/128, TOK/128, 1);
      gemm_mma<<<g, 256>>>(ab, wb, logits, VOCAB_N, 3*DE, VOCAB_N, 0); }
}

// round 5
// speedup vs baseline: 3.0973x; 2.0658x over previous
#include <cuda_runtime.h>
#include <cuda_bf16.h>
#include <cstdint>

#define BB 2
#define LL 1024
#define DM 768
#define DI 1536
#define DS 16
#define DTR 48
#define XD 80            // DT_RANK + 2*D_STATE
#define NL 6
#define VOCAB_N 32000
#define DE 384
#define TOK (BB*LL)      // 2048
#define CH 8             // scan chunks
#define CLEN 128         // steps per chunk
#define DTKP 160         // padded K3 for dt projection (144 -> 160)

typedef __nv_bfloat16 bf16;

// ------------------------- scratch (no allocation allowed) -------------------
__device__ __align__(128) float g_hidden[TOK*DM];
__device__ __align__(128) float g_residual[TOK*DM];
__device__ __align__(128) float g_hs[TOK*DM];
__device__ __align__(128) float g_xz[TOK*2*DI];
__device__ __align__(128) float g_xconv[TOK*DI];
__device__ __align__(128) float g_xdbl[TOK*XD];
__device__ __align__(128) float g_dt[TOK*DI];
__device__ __align__(128) bf16  g_ab[TOK*3*DI];        // split3 activations
__device__ __align__(128) bf16  g_wb[VOCAB_N*3*DE];    // split3 weights
__device__ __align__(128) float g_P[BB*DI*CH*DS];      // scan chunk decay products
__device__ __align__(128) float g_S[BB*DI*CH*DS];      // scan chunk partial states
__device__ __align__(128) float g_hin[BB*DI*CH*DS];    // scan chunk input states

// ------------------------- embed ---------------------------------------------
__global__ void embed_kernel(const int* __restrict__ ids, const int* __restrict__ pos,
                             const float* __restrict__ emb, const float* __restrict__ pemb,
                             float* __restrict__ hidden, float* __restrict__ res)
{
    int idx = blockIdx.x * blockDim.x + threadIdx.x;
    if (idx >= TOK*DM) return;
    int t = idx / DM, c = idx % DM;
    float v;
    if (c < DE) v = emb[(size_t)ids[t]*DE + c];
    else        v = pemb[(size_t)pos[t]*DE + (c-DE)];
    hidden[idx] = v;
    res[idx] = 0.f;
}

__global__ void zero_kernel(float* __restrict__ p, int n)
{
    int i = blockIdx.x * blockDim.x + threadIdx.x;
    if (i < n) p[i] = 0.f;
}

// ---------------- split3 helpers ---------------------------------------------
// A row (stride 3K): [hi | lo | hi] ; B row (stride 3K): [hi | hi | lo]
__device__ __forceinline__ void splitA_write(bf16* row, int K, int k, float v)
{
    bf16 hi = __float2bfloat16(v);
    row[k] = hi;
    row[2*K + k] = hi;
    row[K + k] = __float2bfloat16(v - __bfloat162float(hi));
}
__device__ __forceinline__ void splitB_write(bf16* row, int K, int k, float v)
{
    bf16 hi = __float2bfloat16(v);
    row[k] = hi;
    row[K + k] = hi;
    row[2*K + k] = __float2bfloat16(v - __bfloat162float(hi));
}

__global__ void split3A_kernel(const float* __restrict__ src, int lda, int K, int total,
                               bf16* __restrict__ dst)
{
    int idx = blockIdx.x * blockDim.x + threadIdx.x;
    if (idx >= total) return;
    int m = idx / K, k = idx - m*K;
    splitA_write(dst + (size_t)m*(3*K), K, k, src[(size_t)m*lda + k]);
}
__global__ void split3B_kernel(const float* __restrict__ src, int lda, int K, int total,
                               bf16* __restrict__ dst)
{
    int idx = blockIdx.x * blockDim.x + threadIdx.x;
    if (idx >= total) return;
    int m = idx / K, k = idx - m*K;
    splitB_write(dst + (size_t)m*(3*K), K, k, src[(size_t)m*lda + k]);
}

// dt splits: K=48 -> row stride DTKP (=160), entries 144..159 zero-padded
__global__ void split3A_dt_kernel(const float* __restrict__ src, int total,
                                  bf16* __restrict__ dst)
{
    int idx = blockIdx.x * blockDim.x + threadIdx.x;   // over M*64
    if (idx >= total) return;
    int m = idx >> 6, k = idx & 63;
    bf16* row = dst + (size_t)m*DTKP;
    if (k < DTR) splitA_write(row, DTR, k, src[(size_t)m*XD + k]);
    else         row[96 + k] = __float2bfloat16(0.f);  // 144..159
}
__global__ void split3B_dt_kernel(const float* __restrict__ src, int total,
                                  bf16* __restrict__ dst)
{
    int idx = blockIdx.x * blockDim.x + threadIdx.x;   // over N*64
    if (idx >= total) return;
    int m = idx >> 6, k = idx & 63;
    bf16* row = dst + (size_t)m*DTKP;
    if (k < DTR) splitB_write(row, DTR, k, src[(size_t)m*DTR + k]);
    else         row[96 + k] = __float2bfloat16(0.f);
}

// ---- fused: res += hidden ; out = rmsnorm(res)*w ; + split3A output ---------
__global__ __launch_bounds__(256) void addnorm_kernel(
    const float* __restrict__ h, float* __restrict__ res,
    const float* __restrict__ w, float* __restrict__ out, bf16* __restrict__ outs)
{
    int t = blockIdx.x;
    const float* hp = h + (size_t)t*DM;
    float* rp = res + (size_t)t*DM;
    float v[3];
    float ss = 0.f;
#pragma unroll
    for (int q = 0; q < 3; q++) {
        int i = threadIdx.x + q*256;
        v[q] = hp[i] + rp[i];
        ss += v[q]*v[q];
    }
#pragma unroll
    for (int o = 16; o > 0; o >>= 1) ss += __shfl_xor_sync(0xffffffffu, ss, o);
    __shared__ float red[8];
    if ((threadIdx.x & 31) == 0) red[threadIdx.x >> 5] = ss;
    __syncthreads();
    float tot = 0.f;
#pragma unroll
    for (int q = 0; q < 8; q++) tot += red[q];
    float rstd = rsqrtf(tot * (1.f/(float)DM) + 1e-5f);
    bf16* orow = outs + (size_t)t*(3*DM);
#pragma unroll
    for (int q = 0; q < 3; q++) {
        int i = threadIdx.x + q*256;
        rp[i] = v[q];
        float u = v[q] * rstd * w[i];
        out[(size_t)t*DM + i] = u;
        splitA_write(orow, DM, i, u);
    }
}

// ---- depthwise causal conv (width 4) + bias + silu (+split3A output) -------
__global__ void conv_silu_kernel(const float* __restrict__ xz,
                                 const float* __restrict__ cw,
                                 const float* __restrict__ cb,
                                 float* __restrict__ out, bf16* __restrict__ outs)
{
    int idx = blockIdx.x * blockDim.x + threadIdx.x;
    if (idx >= TOK*DI) return;
    int d = idx % DI;
    int t = idx / DI;
    int l = t % LL;
    float acc = cb[d];
    const float* base = xz + (size_t)t*(2*DI) + d;
#pragma unroll
    for (int j = 0; j < 4; j++) {
        int ll = l - 3 + j;
        if (ll >= 0) acc += cw[d*4+j] * base[(j-3)*(2*DI)];
    }
    float v = acc / (1.f + __expf(-acc));
    out[idx] = v;
    splitA_write(outs + (size_t)t*(3*DI), DI, d, v);
}

// ---------------- chunked selective scan -------------------------------------
// pass A: per (b,d,chunk,n): P = prod dA, S = state from h_in=0
__global__ __launch_bounds__(256) void scanA_kernel(
    const float* __restrict__ xc, const float* __restrict__ dt,
    const float* __restrict__ xd, const float* __restrict__ A_log,
    float* __restrict__ Pv, float* __restrict__ Sv)
{
    int tid = threadIdx.x;
    int u = blockIdx.x * 16 + (tid >> 4);   // (pair, chunk)
    int n = tid & 15;
    int p = u >> 3;                          // CH=8
    int c = u & 7;
    int b = p / DI, d = p - b*DI;
    float A = -__expf(A_log[d*DS + n]);
    const float* xcb = xc + (size_t)b*LL*DI + d;
    const float* dtb = dt + (size_t)b*LL*DI + d;
    const float* xdb = xd + (size_t)b*LL*XD + DTR + n;
    int l0 = c * CLEN;
    float P = 1.f, h = 0.f;
#pragma unroll 4
    for (int i = 0; i < CLEN; i++) {
        int l = l0 + i;
        float xv  = xcb[(size_t)l*DI];
        float dtv = dtb[(size_t)l*DI];
        float Bv  = xdb[(size_t)l*XD];
        float dA  = __expf(dtv * A);
        P *= dA;
        h = dA*h + (dtv*xv)*Bv;
    }
    Pv[(size_t)u*DS + n] = P;
    Sv[(size_t)u*DS + n] = h;
}

// pass B: serial combine over chunks -> h_in per chunk
__global__ void scanB_kernel(const float* __restrict__ Pv, const float* __restrict__ Sv,
                             float* __restrict__ hin)
{
    int g = blockIdx.x * blockDim.x + threadIdx.x;   // p*DS + n
    if (g >= BB*DI*DS) return;
    int p = g / DS, n = g - p*DS;
    float h = 0.f;
#pragma unroll
    for (int c = 0; c < CH; c++) {
        size_t idx = ((size_t)p*CH + c)*DS + n;
        hin[idx] = h;
        h = Pv[idx]*h + Sv[idx];
    }
}

// pass C: rescan chunk from correct h_in, produce y (split3A bf16)
__global__ __launch_bounds__(256) void scanC_kernel(
    const float* __restrict__ xc, const float* __restrict__ dt,
    const float* __restrict__ xd, const float* __restrict__ xz,
    const float* __restrict__ A_log, const float* __restrict__ Dv,
    const float* __restrict__ hin, bf16* __restrict__ ys)
{
    int tid = threadIdx.x;
    int u = blockIdx.x * 16 + (tid >> 4);
    int n = tid & 15;
    int p = u >> 3;
    int c = u & 7;
    int b = p / DI, d = p - b*DI;
    float A = -__expf(A_log[d*DS + n]);
    float Dval = Dv[d];
    const float* xcb = xc + (size_t)b*LL*DI + d;
    const float* dtb = dt + (size_t)b*LL*DI + d;
    const float* xdb = xd + (size_t)b*LL*XD + DTR + n;
    const float* xzb = xz + (size_t)b*LL*(2*DI) + DI + d;
    bf16* yb = ys + (size_t)b*LL*(3*DI);
    int l0 = c * CLEN;
    float h = hin[(size_t)u*DS + n];
#pragma unroll 4
    for (int i = 0; i < CLEN; i++) {
        int l = l0 + i;
        float xv  = xcb[(size_t)l*DI];
        float dtv = dtb[(size_t)l*DI];
        float Bv  = xdb[(size_t)l*XD];
        float Cv  = xdb[(size_t)l*XD + DS];
        float dA  = __expf(dtv * A);
        h = dA*h + (dtv*xv)*Bv;
        float part = h*Cv;
        part += __shfl_xor_sync(0xffffffffu, part, 1);
        part += __shfl_xor_sync(0xffffffffu, part, 2);
        part += __shfl_xor_sync(0xffffffffu, part, 4);
        part += __shfl_xor_sync(0xffffffffu, part, 8);
        if (n == 0) {
            float z = xzb[(size_t)l*(2*DI)];
            float sig = 1.f / (1.f + __expf(-z));
            float v = (part + xv*Dval) * (z * sig);
            splitA_write(yb + (size_t)l*(3*DI), DI, d, v);
        }
    }
}

// --------------------------- tensor-core GEMM --------------------------------
// C[m,n] = sum_k A[m,k]*B[n,k]. 128x128 block, BK=32, cp.async(16B) dbl-buffered.
// grid = (M/128, ceil(N/128), ksplit). katomic: atomicAdd epilogue. epi=1: softplus+bias.
__device__ __forceinline__ void ldsm_x4(uint32_t* r, uint32_t addr){
    asm volatile("ldmatrix.sync.aligned.m8n8.x4.shared.b16 {%0,%1,%2,%3}, [%4];"
      : "=r"(r[0]),"=r"(r[1]),"=r"(r[2]),"=r"(r[3]) : "r"(addr));
}
__device__ __forceinline__ void mma_bf16(float* c, const uint32_t* a, const uint32_t* b){
    asm volatile("mma.sync.aligned.m16n8k16.row.col.f32.bf16.bf16.f32 "
      "{%0,%1,%2,%3}, {%4,%5,%6,%7}, {%8,%9}, {%0,%1,%2,%3};"
      : "+f"(c[0]),"+f"(c[1]),"+f"(c[2]),"+f"(c[3])
      : "r"(a[0]),"r"(a[1]),"r"(a[2]),"r"(a[3]), "r"(b[0]),"r"(b[1]));
}
__device__ __forceinline__ void cp16(uint32_t daddr, const void* gptr, uint32_t srcsz){
    asm volatile("cp.async.cg.shared.global [%0], [%1], 16, %2;\n"
      :: "r"(daddr), "l"(gptr), "r"(srcsz));
}

#define SSTRIDE 40
#define STG_HALF (128*SSTRIDE)

__global__ __launch_bounds__(256,2) void gemm_mma(
    const bf16* __restrict__ A, const bf16* __restrict__ B,
    float* __restrict__ C, int N, int K2, int ldc,
    int katomic, int epi, const float* __restrict__ bias)
{
    __shared__ __align__(16) bf16 sA[2*STG_HALF];
    __shared__ __align__(16) bf16 sB[2*STG_HALF];
    const int tid = threadIdx.x;
    const int lane = tid & 31, wid = tid >> 5;
    const int wm = wid & 1, wn = wid >> 1;
    const int bm = blockIdx.x * 128, bn = blockIdx.y * 128;

    const int ksplit = gridDim.z;
    const int per = (K2 / 32) / ksplit;
    const int kbeg = blockIdx.z * per * 32;
    const int iters = per;

    // 16B chunk mapping: 2 chunks per matrix per thread
    const int r0 = tid >> 2,            c0 = (tid & 3) * 8;
    const int r1 = (tid + 256) >> 2,    c1 = ((tid + 256) & 3) * 8;

    uint32_t sAb = (uint32_t)__cvta_generic_to_shared(sA);
    uint32_t sBb = (uint32_t)__cvta_generic_to_shared(sB);

    const int bw0 = bn + r0, bw1 = bn + r1;
    const bool bv0 = bw0 < N, bv1 = bw1 < N;
    const bf16* Bq0 = B + (size_t)(bv0 ? bw0 : 0)*K2;
    const bf16* Bq1 = B + (size_t)(bv1 ? bw1 : 0)*K2;
    const bf16* Aq0 = A + (size_t)(bm + r0)*K2;
    const bf16* Aq1 = A + (size_t)(bm + r1)*K2;

    float acc[4][4][4];
#pragma unroll
    for (int i = 0; i < 4; i++)
#pragma unroll
        for (int j = 0; j < 4; j++)
#pragma unroll
            for (int q = 0; q < 4; q++) acc[i][j][q] = 0.f;

    // prologue: stage 0
    {
        int k = kbeg;
        cp16(sAb + (uint32_t)(r0*SSTRIDE + c0)*2, Aq0 + k + c0, 16u);
        cp16(sAb + (uint32_t)(r1*SSTRIDE + c1)*2, Aq1 + k + c1, 16u);
        cp16(sBb + (uint32_t)(r0*SSTRIDE + c0)*2, Bq0 + k + c0, bv0 ? 16u : 0u);
        cp16(sBb + (uint32_t)(r1*SSTRIDE + c1)*2, Bq1 + k + c1, bv1 ? 16u : 0u);
        asm volatile("cp.async.commit_group;\n" ::: "memory");
    }

    const int ar  = lane & 15;
    const int ak  = (lane >> 4) * 8;
    const int brr = (lane & 7) + ((lane >> 4) & 1)*8;
    const int bk  = ((lane >> 3) & 1) * 8;

    int buf = 0;
    for (int it = 0; it < iters; it++) {
        asm volatile("cp.async.wait_group 0;\n" ::: "memory");
        __syncthreads();
        if (it + 1 < iters) {
            int k = kbeg + (it+1)*32;
            uint32_t so = (uint32_t)(buf ^ 1) * (STG_HALF*2);
            cp16(sAb + so + (uint32_t)(r0*SSTRIDE + c0)*2, Aq0 + k + c0, 16u);
            cp16(sAb + so + (uint32_t)(r1*SSTRIDE + c1)*2, Aq1 + k + c1, 16u);
            cp16(sBb + so + (uint32_t)(r0*SSTRIDE + c0)*2, Bq0 + k + c0, bv0 ? 16u : 0u);
            cp16(sBb + so + (uint32_t)(r1*SSTRIDE + c1)*2, Bq1 + k + c1, bv1 ? 16u : 0u);
            asm volatile("cp.async.commit_group;\n" ::: "memory");
        }
        uint32_t sAc = sAb + (uint32_t)buf * (STG_HALF*2);
        uint32_t sBc = sBb + (uint32_t)buf * (STG_HALF*2);
#pragma unroll
        for (int kk = 0; kk < 2; kk++) {
            uint32_t afr[4][4], bfr[4][2];
#pragma unroll
            for (int mi = 0; mi < 4; mi++) {
                int row = wm*64 + mi*16 + ar;
                ldsm_x4(afr[mi], sAc + (uint32_t)(row*SSTRIDE + kk*16 + ak)*2);
            }
#pragma unroll
            for (int np = 0; np < 2; np++) {
                int row = wn*32 + np*16 + brr;
                uint32_t q4[4];
                ldsm_x4(q4, sBc + (uint32_t)(row*SSTRIDE + kk*16 + bk)*2);
                bfr[np*2+0][0]=q4[0]; bfr[np*2+0][1]=q4[1];
                bfr[np*2+1][0]=q4[2]; bfr[np*2+1][1]=q4[3];
            }
#pragma unroll
            for (int mi = 0; mi < 4; mi++)
#pragma unroll
                for (int ni = 0; ni < 4; ni++)
                    mma_bf16(acc[mi][ni], afr[mi], bfr[ni]);
        }
        buf ^= 1;
    }

    const int grp = lane >> 2, qd = lane & 3;
#pragma unroll
    for (int mi = 0; mi < 4; mi++) {
        int m = bm + wm*64 + mi*16 + grp;
#pragma unroll
        for (int ni = 0; ni < 4; ni++) {
            int n = bn + wn*32 + ni*8 + qd*2;
            if (n < N) {
                float c0v = acc[mi][ni][0], c1v = acc[mi][ni][1];
                float c2v = acc[mi][ni][2], c3v = acc[mi][ni][3];
                if (epi == 1) {
                    float b0 = bias[n], b1 = bias[n+1];
                    float x0 = c0v + b0, x1 = c1v + b1, x2 = c2v + b0, x3 = c3v + b1;
                    c0v = (x0 > 20.f) ? x0 : log1pf(__expf(x0));
                    c1v = (x1 > 20.f) ? x1 : log1pf(__expf(x1));
                    c2v = (x2 > 20.f) ? x2 : log1pf(__expf(x2));
                    c3v = (x3 > 20.f) ? x3 : log1pf(__expf(x3));
                }
                if (katomic) {
                    atomicAdd(&C[(size_t)m*ldc + n],       c0v);
                    if (n+1 < N) atomicAdd(&C[(size_t)m*ldc + n+1], c1v);
                    atomicAdd(&C[(size_t)(m+8)*ldc + n],   c2v);
                    if (n+1 < N) atomicAdd(&C[(size_t)(m+8)*ldc + n+1], c3v);
                } else {
                    *(float2*)(&C[(size_t)m*ldc + n])     = make_float2(c0v, c1v);
                    *(float2*)(&C[(size_t)(m+8)*ldc + n]) = make_float2(c2v, c3v);
                }
            }
        }
    }
}

// ------------------------------- driver --------------------------------------
extern "C" void kernel_launch(void* const* d_in, const int* in_sizes, int n_in,
                              void* d_out, int out_size)
{
    (void)in_sizes; (void)n_in; (void)out_size;
    const int*   ids   = (const int*)d_in[0];
    const int*   pos   = (const int*)d_in[1];
    const float* emb   = (const float*)d_in[2];
    const float* pemb  = (const float*)d_in[3];
    const float* normw = (const float*)d_in[4];
    const float* inw   = (const float*)d_in[5];
    const float* convw = (const float*)d_in[6];
    const float* convb = (const float*)d_in[7];
    const float* xpw   = (const float*)d_in[8];
    const float* dtw   = (const float*)d_in[9];
    const float* dtb   = (const float*)d_in[10];
    const float* Alog  = (const float*)d_in[11];
    const float* Dvec  = (const float*)d_in[12];
    const float* outw  = (const float*)d_in[13];
    const float* normf = (const float*)d_in[14];
    float* logits = (float*)d_out;

    float *hid, *res, *hs, *xz, *xc, *xd, *dtv, *Pv, *Sv, *hin;
    bf16 *ab, *wb;
    cudaGetSymbolAddress((void**)&hid, g_hidden);
    cudaGetSymbolAddress((void**)&res, g_residual);
    cudaGetSymbolAddress((void**)&hs,  g_hs);
    cudaGetSymbolAddress((void**)&xz,  g_xz);
    cudaGetSymbolAddress((void**)&xc,  g_xconv);
    cudaGetSymbolAddress((void**)&xd,  g_xdbl);
    cudaGetSymbolAddress((void**)&dtv, g_dt);
    cudaGetSymbolAddress((void**)&ab,  g_ab);
    cudaGetSymbolAddress((void**)&wb,  g_wb);
    cudaGetSymbolAddress((void**)&Pv,  g_P);
    cudaGetSymbolAddress((void**)&Sv,  g_S);
    cudaGetSymbolAddress((void**)&hin, g_hin);

    embed_kernel<<<(TOK*DM + 255)/256, 256>>>(ids, pos, emb, pemb, hid, res);

    for (int layer = 0; layer < NL; layer++) {
        addnorm_kernel<<<TOK, 256>>>(hid, res, normw + (size_t)layer*DM, hs, ab);

        // xz = hs @ in_proj^T : N=3072, K3=2304
        split3B_kernel<<<(2*DI*DM + 255)/256, 256>>>(inw + (size_t)layer*2*DI*DM, DM, DM, 2*DI*DM, wb);
        { dim3 g(TOK/128, 2*DI/128, 1);
          gemm_mma<<<g, 256>>>(ab, wb, xz, 2*DI, 3*DM, 2*DI, 0, 0, nullptr); }

        conv_silu_kernel<<<(TOK*DI + 255)/256, 256>>>(
            xz, convw + (size_t)layer*DI*4, convb + (size_t)layer*DI, xc, ab);

        // x_dbl = xc @ x_proj^T : N=80, K3=4608, split-K=8
        split3B_kernel<<<(XD*DI + 255)/256, 256>>>(xpw + (size_t)layer*XD*DI, DI, DI, XD*DI, wb);
        zero_kernel<<<(TOK*XD + 255)/256, 256>>>(xd, TOK*XD);
        { dim3 g(TOK/128, 1, 8);
          gemm_mma<<<g, 256>>>(ab, wb, xd, XD, 3*DI, XD, 1, 0, nullptr); }

        // dt = softplus(x_dbl[:, :48] @ dt_proj^T + dtb) : tensor core, K padded 160
        split3A_dt_kernel<<<(TOK*64 + 255)/256, 256>>>(xd, TOK*64, ab);
        split3B_dt_kernel<<<(DI*64 + 255)/256, 256>>>(dtw + (size_t)layer*DI*DTR, DI*64, wb);
        { dim3 g(TOK/128, DI/128, 1);
          gemm_mma<<<g, 256>>>(ab, wb, dtv, DI, DTKP, DI, 0, 1, dtb + (size_t)layer*DI); }

        // chunked selective scan
        scanA_kernel<<<(BB*DI*CH)/16, 256>>>(xc, dtv, xd, Alog + (size_t)layer*DI*DS, Pv, Sv);
        scanB_kernel<<<(BB*DI*DS + 255)/256, 256>>>(Pv, Sv, hin);
        scanC_kernel<<<(BB*DI*CH)/16, 256>>>(xc, dtv, xd, xz,
                                             Alog + (size_t)layer*DI*DS,
                                             Dvec + (size_t)layer*DI, hin, ab);

        // hid = y @ out_proj^T : N=768, K3=4608, split-K=3
        split3B_kernel<<<(DM*DI + 255)/256, 256>>>(outw + (size_t)layer*DM*DI, DI, DI, DM*DI, wb);
        zero_kernel<<<(TOK*DM + 255)/256, 256>>>(hid, TOK*DM);
        { dim3 g(TOK/128, DM/128, 3);
          gemm_mma<<<g, 256>>>(ab, wb, hid, DM, 3*DI, DM, 1, 0, nullptr); }
    }

    addnorm_kernel<<<TOK, 256>>>(hid, res, normf, hs, ab);

    // logits = hs[:, :384] @ emb^T : N=32000, K3=1152
    split3A_kernel<<<(TOK*DE + 255)/256, 256>>>(hs, DM, DE, TOK*DE, ab);
    split3B_kernel<<<(VOCAB_N*DE + 255)/256, 256>>>(emb, DE, DE, VOCAB_N*DE, wb);
    { dim3 g(TOK/128, (VOCAB_N + 127)/128, 1);
      gemm_mma<<<g, 256>>>(ab, wb, logits, VOCAB_N, 3*DE, VOCAB_N, 0, 0, nullptr); }
}